// round 13
// baseline (speedup 1.0000x reference)
#include <cuda_runtime.h>
#include <math.h>

constexpr int kN   = 50000;
constexpr int kE   = 800000;
constexpr int kIN  = 512;
constexpr int kHID = 64;
constexpr int kOUT = 40;
constexpr int kL   = 16;

// ---------------- device scratch (static allocations only) ----------------
__device__ float g_h0[kN * kHID];          // relu(X @ W_in + b_in)
__device__ float g_h [kN * kHID];          // current layer state
__device__ float g_f [kN * kHID];          // 0.9 * Dst^-1/2 A Dsrc^-1/2 h
__device__ float g_M1[kL * kHID * kHID];   // (1-b)I + b*W1
__device__ float g_M2[kL * kHID * kHID];   // 0.1*((1-b)I + b*W2)
__device__ int   g_rowptr[kN + 1];
__device__ int   g_col[kE];
__device__ float g_w  [kE];
__device__ int   g_degin [kN];
__device__ int   g_degout[kN];
__device__ int   g_cnt   [kN];
__device__ float g_nsrc[kN];
__device__ float g_cdst[kN];

// ---------------- graph preprocessing ----------------
__global__ void k_zero() {
    int i = blockIdx.x * blockDim.x + threadIdx.x;
    if (i < kN) { g_degin[i] = 0; g_degout[i] = 0; g_cnt[i] = 0; }
}

__global__ void k_degree(const int* __restrict__ src, const int* __restrict__ dst) {
    int e = blockIdx.x * blockDim.x + threadIdx.x;
    if (e < kE) {
        atomicAdd(&g_degout[src[e]], 1);
        atomicAdd(&g_degin [dst[e]], 1);
    }
}

// single-block exclusive scan of deg_in -> rowptr
__global__ void k_scan() {
    __shared__ int sh[1024];
    __shared__ int carry_sh;
    int t = threadIdx.x;
    if (t == 0) carry_sh = 0;
    __syncthreads();
    for (int base = 0; base < kN; base += 1024) {
        int v = (base + t < kN) ? g_degin[base + t] : 0;
        sh[t] = v;
        __syncthreads();
        #pragma unroll
        for (int off = 1; off < 1024; off <<= 1) {
            int add = (t >= off) ? sh[t - off] : 0;
            __syncthreads();
            sh[t] += add;
            __syncthreads();
        }
        int c = carry_sh;
        if (base + t < kN) g_rowptr[base + t] = c + sh[t] - v;
        __syncthreads();
        if (t == 0) carry_sh = c + sh[1023];
        __syncthreads();
    }
    if (t == 0) g_rowptr[kN] = carry_sh;
}

__global__ void k_norm() {
    int i = blockIdx.x * blockDim.x + threadIdx.x;
    if (i < kN) {
        g_nsrc[i] = rsqrtf(fmaxf((float)g_degout[i], 1.0f));
        g_cdst[i] = 0.9f * rsqrtf(fmaxf((float)g_degin[i], 1.0f));   // (1-ALPHA)*norm_dst
    }
}

__global__ void k_fill(const int* __restrict__ src, const int* __restrict__ dst) {
    int e = blockIdx.x * blockDim.x + threadIdx.x;
    if (e < kE) {
        int d = dst[e], s = src[e];
        int pos = g_rowptr[d] + atomicAdd(&g_cnt[d], 1);
        g_col[pos] = s;
        g_w[pos]   = g_nsrc[s];
    }
}

// M1 = (1-beta)I + beta*W1 ; M2 = ALPHA*((1-beta)I + beta*W2)
__global__ void k_weights(const float* __restrict__ W1, const float* __restrict__ W2) {
    int idx = blockIdx.x * blockDim.x + threadIdx.x;
    if (idx < kL * kHID * kHID) {
        int l = idx >> 12;
        int k = (idx >> 6) & 63;
        int j = idx & 63;
        float beta = logf(0.5f / (float)(l + 1) + 1.0f);
        float id   = (k == j) ? (1.0f - beta) : 0.0f;
        g_M1[idx] = beta * W1[idx] + id;
        g_M2[idx] = 0.1f * (beta * W2[idx] + id);
    }
}

// ---------------- input GEMM: h0 = relu(X[50000,512] @ W[512,64] + b) ----------------
constexpr int FSTR = 68;   // padded smem row stride (floats), keeps float4 alignment

__global__ void k_ingemm(const float* __restrict__ X, const float* __restrict__ W,
                         const float* __restrict__ bias) {
    __shared__ float Fs[32 * FSTR];   // [k][row] transposed feature tile
    __shared__ float Ws[32 * FSTR];   // [k][col]
    int tid  = threadIdx.x;
    int tcol = tid & 15;
    int trow = tid >> 4;
    int row0 = blockIdx.x * 64;
    float acc[4][4] = {};

    for (int kc = 0; kc < kIN; kc += 32) {
        #pragma unroll
        for (int i = 0; i < 2; i++) {
            int fid = tid + i * 256;            // 0..511 float4 slots
            int r   = fid >> 3;                 // 0..63
            int k4  = fid & 7;                  // 0..7
            int grow = row0 + r;
            float4 v = make_float4(0.f, 0.f, 0.f, 0.f);
            if (grow < kN) v = *(const float4*)&X[grow * kIN + kc + k4 * 4];
            Fs[(k4 * 4 + 0) * FSTR + r] = v.x;
            Fs[(k4 * 4 + 1) * FSTR + r] = v.y;
            Fs[(k4 * 4 + 2) * FSTR + r] = v.z;
            Fs[(k4 * 4 + 3) * FSTR + r] = v.w;
        }
        #pragma unroll
        for (int i = 0; i < 2; i++) {
            int fid = tid + i * 256;
            int k   = fid >> 4;                 // 0..31
            int c4  = fid & 15;                 // 0..15
            *(float4*)&Ws[k * FSTR + c4 * 4] = *(const float4*)&W[(kc + k) * kHID + c4 * 4];
        }
        __syncthreads();
        #pragma unroll 8
        for (int k = 0; k < 32; k++) {
            float4 a = *(float4*)&Fs[k * FSTR + trow * 4];
            float4 b = *(float4*)&Ws[k * FSTR + tcol * 4];
            float av[4] = {a.x, a.y, a.z, a.w};
            float bv[4] = {b.x, b.y, b.z, b.w};
            #pragma unroll
            for (int i = 0; i < 4; i++)
                #pragma unroll
                for (int j = 0; j < 4; j++)
                    acc[i][j] += av[i] * bv[j];
        }
        __syncthreads();
    }
    #pragma unroll
    for (int i = 0; i < 4; i++) {
        int grow = row0 + trow * 4 + i;
        if (grow < kN) {
            float4 o;
            o.x = fmaxf(acc[i][0] + bias[tcol * 4 + 0], 0.f);
            o.y = fmaxf(acc[i][1] + bias[tcol * 4 + 1], 0.f);
            o.z = fmaxf(acc[i][2] + bias[tcol * 4 + 2], 0.f);
            o.w = fmaxf(acc[i][3] + bias[tcol * 4 + 3], 0.f);
            *(float4*)&g_h0[grow * kHID + tcol * 4] = o;
        }
    }
}

// ---------------- SpMM: g_f[i] = 0.9*ndst[i] * sum_e w_e * h[col_e] ----------------
__global__ void k_spmm(int first) {
    int gw   = (blockIdx.x * blockDim.x + threadIdx.x) >> 5;
    int lane = threadIdx.x & 31;
    if (gw >= kN) return;
    const float2* __restrict__ h2 = (const float2*)(first ? g_h0 : g_h);
    int beg = g_rowptr[gw], end = g_rowptr[gw + 1];
    float ax = 0.f, ay = 0.f;
    int e = beg;
    for (; e + 4 <= end; e += 4) {
        int   c0 = g_col[e],   c1 = g_col[e+1], c2 = g_col[e+2], c3 = g_col[e+3];
        float w0 = g_w[e],     w1 = g_w[e+1],   w2 = g_w[e+2],   w3 = g_w[e+3];
        float2 v0 = h2[c0 * 32 + lane];
        float2 v1 = h2[c1 * 32 + lane];
        float2 v2 = h2[c2 * 32 + lane];
        float2 v3 = h2[c3 * 32 + lane];
        ax += w0 * v0.x + w1 * v1.x + w2 * v2.x + w3 * v3.x;
        ay += w0 * v0.y + w1 * v1.y + w2 * v2.y + w3 * v3.y;
    }
    for (; e < end; e++) {
        int c = g_col[e]; float w = g_w[e];
        float2 v = h2[c * 32 + lane];
        ax += w * v.x; ay += w * v.y;
    }
    float cd = g_cdst[gw];
    ((float2*)g_f)[gw * 32 + lane] = make_float2(cd * ax, cd * ay);
}

// ---------------- layer GEMM: h = relu(f@M1 + h0@M2 + bias) ----------------
constexpr int LG_SMEM = (4 * 64 * FSTR + 64) * (int)sizeof(float);   // ~70 KB

__global__ void k_layergemm(int l, const float* __restrict__ bias) {
    extern __shared__ float lsm[];
    float* Fs  = lsm;
    float* F0s = lsm + 64 * FSTR;
    float* M1s = lsm + 2 * 64 * FSTR;
    float* M2s = lsm + 3 * 64 * FSTR;
    float* bs  = lsm + 4 * 64 * FSTR;
    int tid  = threadIdx.x;
    int tcol = tid & 15;
    int trow = tid >> 4;
    int row0 = blockIdx.x * 64;
    const float* __restrict__ M1g = g_M1 + l * kHID * kHID;
    const float* __restrict__ M2g = g_M2 + l * kHID * kHID;

    #pragma unroll
    for (int i = 0; i < 4; i++) {
        int fid = tid + i * 256;           // 0..1023 float4 slots
        int r   = fid >> 4;                // 0..63
        int k4  = fid & 15;                // 0..15
        int grow = row0 + r;
        float4 v  = make_float4(0.f, 0.f, 0.f, 0.f);
        float4 v0 = v;
        if (grow < kN) {
            v  = *(const float4*)&g_f [grow * kHID + k4 * 4];
            v0 = *(const float4*)&g_h0[grow * kHID + k4 * 4];
        }
        Fs [(k4 * 4 + 0) * FSTR + r] = v.x;
        Fs [(k4 * 4 + 1) * FSTR + r] = v.y;
        Fs [(k4 * 4 + 2) * FSTR + r] = v.z;
        Fs [(k4 * 4 + 3) * FSTR + r] = v.w;
        F0s[(k4 * 4 + 0) * FSTR + r] = v0.x;
        F0s[(k4 * 4 + 1) * FSTR + r] = v0.y;
        F0s[(k4 * 4 + 2) * FSTR + r] = v0.z;
        F0s[(k4 * 4 + 3) * FSTR + r] = v0.w;
        int k  = fid >> 4;
        int c4 = fid & 15;
        *(float4*)&M1s[k * FSTR + c4 * 4] = *(const float4*)&M1g[k * kHID + c4 * 4];
        *(float4*)&M2s[k * FSTR + c4 * 4] = *(const float4*)&M2g[k * kHID + c4 * 4];
    }
    if (tid < 64) bs[tid] = bias[tid];
    __syncthreads();

    float acc[4][4] = {};
    #pragma unroll 8
    for (int k = 0; k < 64; k++) {
        float4 a  = *(float4*)&Fs [k * FSTR + trow * 4];
        float4 a0 = *(float4*)&F0s[k * FSTR + trow * 4];
        float4 b1 = *(float4*)&M1s[k * FSTR + tcol * 4];
        float4 b2 = *(float4*)&M2s[k * FSTR + tcol * 4];
        float av [4] = {a.x,  a.y,  a.z,  a.w};
        float a0v[4] = {a0.x, a0.y, a0.z, a0.w};
        float b1v[4] = {b1.x, b1.y, b1.z, b1.w};
        float b2v[4] = {b2.x, b2.y, b2.z, b2.w};
        #pragma unroll
        for (int i = 0; i < 4; i++)
            #pragma unroll
            for (int j = 0; j < 4; j++)
                acc[i][j] += av[i] * b1v[j] + a0v[i] * b2v[j];
    }
    #pragma unroll
    for (int i = 0; i < 4; i++) {
        int grow = row0 + trow * 4 + i;
        if (grow < kN) {
            float4 o;
            o.x = fmaxf(acc[i][0] + bs[tcol * 4 + 0], 0.f);
            o.y = fmaxf(acc[i][1] + bs[tcol * 4 + 1], 0.f);
            o.z = fmaxf(acc[i][2] + bs[tcol * 4 + 2], 0.f);
            o.w = fmaxf(acc[i][3] + bs[tcol * 4 + 3], 0.f);
            *(float4*)&g_h[grow * kHID + tcol * 4] = o;
        }
    }
}

// ---------------- output: log_softmax(h @ W_out + b_out) ----------------
__global__ void k_out(const float* __restrict__ Wo, const float* __restrict__ bo,
                      float* __restrict__ out) {
    __shared__ float Ws[kHID * kOUT];
    __shared__ float bs[kOUT];
    int tid = threadIdx.x;
    for (int i = tid; i < kHID * kOUT; i += 256) Ws[i] = Wo[i];
    if (tid < kOUT) bs[tid] = bo[tid];
    __syncthreads();
    int warp = tid >> 5;
    int lane = tid & 31;
    int node = blockIdx.x * 8 + warp;
    if (node >= kN) return;
    float2 hv = ((const float2*)g_h)[node * 32 + lane];
    float acc0 = bs[lane];
    float acc1 = (lane < 8) ? bs[32 + lane] : 0.f;
    #pragma unroll
    for (int k = 0; k < kHID; k++) {
        float val = __shfl_sync(0xffffffffu, (k & 1) ? hv.y : hv.x, k >> 1);
        acc0 += val * Ws[k * kOUT + lane];
        if (lane < 8) acc1 += val * Ws[k * kOUT + 32 + lane];
    }
    float m = fmaxf(acc0, (lane < 8) ? acc1 : -INFINITY);
    #pragma unroll
    for (int off = 16; off > 0; off >>= 1)
        m = fmaxf(m, __shfl_xor_sync(0xffffffffu, m, off));
    float s = expf(acc0 - m) + ((lane < 8) ? expf(acc1 - m) : 0.f);
    #pragma unroll
    for (int off = 16; off > 0; off >>= 1)
        s += __shfl_xor_sync(0xffffffffu, s, off);
    float lse = m + logf(s);
    out[node * kOUT + lane] = acc0 - lse;
    if (lane < 8) out[node * kOUT + 32 + lane] = acc1 - lse;
}

// ---------------- launch ----------------
extern "C" void kernel_launch(void* const* d_in, const int* in_sizes, int n_in,
                              void* d_out, int out_size) {
    const float* features = (const float*)d_in[0];
    const float* W_in     = (const float*)d_in[1];
    const float* b_in     = (const float*)d_in[2];
    const float* W1       = (const float*)d_in[3];
    const float* W2       = (const float*)d_in[4];
    const float* b        = (const float*)d_in[5];
    const float* W_out    = (const float*)d_in[6];
    const float* b_out    = (const float*)d_in[7];
    const int*   src      = (const int*)d_in[8];
    const int*   dst      = (const int*)d_in[9];
    float* out = (float*)d_out;

    cudaFuncSetAttribute(k_layergemm, cudaFuncAttributeMaxDynamicSharedMemorySize, LG_SMEM);

    int gridN = (kN + 255) / 256;
    int gridE = (kE + 255) / 256;
    int gridW = (kL * kHID * kHID + 255) / 256;
    int gridG = (kN + 63) / 64;         // 782 GEMM row-blocks
    int gridS = (kN + 7) / 8;           // 6250 warp-per-row blocks

    k_zero  <<<gridN, 256>>>();
    k_degree<<<gridE, 256>>>(src, dst);
    k_scan  <<<1, 1024>>>();
    k_norm  <<<gridN, 256>>>();
    k_fill  <<<gridE, 256>>>(src, dst);
    k_weights<<<gridW, 256>>>(W1, W2);
    k_ingemm<<<gridG, 256>>>(features, W_in, b_in);

    for (int l = 0; l < kL; l++) {
        k_spmm<<<gridS, 256>>>(l == 0 ? 1 : 0);
        k_layergemm<<<gridG, 256, LG_SMEM>>>(l, b + l * kHID);
    }
    k_out<<<gridS, 256>>>(W_out, b_out, out);
}

// round 15
// speedup vs baseline: 1.0620x; 1.0620x over previous
#include <cuda_runtime.h>
#include <math.h>

constexpr int kN   = 50000;
constexpr int kE   = 800000;
constexpr int kIN  = 512;
constexpr int kHID = 64;
constexpr int kOUT = 40;
constexpr int kL   = 16;
constexpr int kSB  = (kN + 1023) / 1024;   // 49 scan blocks

// ---------------- device scratch (static allocations only) ----------------
__device__ float g_h0[kN * kHID];          // relu(X @ W_in + b_in)
__device__ float g_hA[kN * kHID];          // ping-pong state buffers
__device__ float g_hB[kN * kHID];
__device__ float g_M1[kL * kHID * kHID];   // (1-b)I + b*W1
__device__ float g_M2[kL * kHID * kHID];   // 0.1*((1-b)I + b*W2)
__device__ int   g_rowptr[kN + 1];
__device__ int   g_col[kE];
__device__ float g_w  [kE];
__device__ int   g_degin [kN];
__device__ int   g_degout[kN];
__device__ int   g_cnt   [kN];
__device__ int   g_bsum[kSB];
__device__ int   g_boff[kSB];

// ---------------- helpers ----------------
__device__ __forceinline__ void cpasync16(unsigned int smem, const void* gmem) {
    asm volatile("cp.async.cg.shared.global [%0], [%1], 16;\n" :: "r"(smem), "l"(gmem));
}
__device__ __forceinline__ unsigned long long fma2(unsigned long long a,
                                                   unsigned long long b,
                                                   unsigned long long c) {
    unsigned long long d;
    asm("fma.rn.f32x2 %0, %1, %2, %3;" : "=l"(d) : "l"(a), "l"(b), "l"(c));
    return d;
}
__device__ __forceinline__ unsigned long long pack2(float x) {
    unsigned long long d;
    asm("mov.b64 %0, {%1, %1};" : "=l"(d) : "f"(x));
    return d;
}
__device__ __forceinline__ float2 unpack2(unsigned long long v) {
    float x, y;
    asm("mov.b64 {%0, %1}, %2;" : "=f"(x), "=f"(y) : "l"(v));
    return make_float2(x, y);
}

// ---------------- preprocessing ----------------
// zero counters + build M1/M2 in one kernel (disjoint outputs)
__global__ void k_init(const float* __restrict__ W1, const float* __restrict__ W2) {
    int idx = blockIdx.x * blockDim.x + threadIdx.x;
    if (idx < kN) { g_degin[idx] = 0; g_degout[idx] = 0; g_cnt[idx] = 0; }
    if (idx < kL * kHID * kHID) {
        int l = idx >> 12;
        int k = (idx >> 6) & 63;
        int j = idx & 63;
        float beta = logf(0.5f / (float)(l + 1) + 1.0f);
        float id   = (k == j) ? (1.0f - beta) : 0.0f;
        g_M1[idx] = beta * W1[idx] + id;
        g_M2[idx] = 0.1f * (beta * W2[idx] + id);
    }
}

__global__ void k_degree(const int* __restrict__ src, const int* __restrict__ dst) {
    int e = blockIdx.x * blockDim.x + threadIdx.x;
    if (e < kE) {
        atomicAdd(&g_degout[src[e]], 1);
        atomicAdd(&g_degin [dst[e]], 1);
    }
}

// hierarchical exclusive scan of deg_in -> rowptr
__global__ void k_scan1() {
    __shared__ int wsum[32];
    int t = threadIdx.x;
    int lane = t & 31, wid = t >> 5;
    int i = blockIdx.x * 1024 + t;
    int v = (i < kN) ? g_degin[i] : 0;
    int x = v;
    #pragma unroll
    for (int off = 1; off < 32; off <<= 1) {
        int y = __shfl_up_sync(0xffffffffu, x, off);
        if (lane >= off) x += y;
    }
    if (lane == 31) wsum[wid] = x;
    __syncthreads();
    if (wid == 0) {
        int s = wsum[lane];
        #pragma unroll
        for (int off = 1; off < 32; off <<= 1) {
            int y = __shfl_up_sync(0xffffffffu, s, off);
            if (lane >= off) s += y;
        }
        wsum[lane] = s;
    }
    __syncthreads();
    int woff = (wid > 0) ? wsum[wid - 1] : 0;
    if (i < kN) g_rowptr[i] = woff + x - v;       // block-local exclusive
    if (t == 1023) g_bsum[blockIdx.x] = woff + x; // block total
}

__global__ void k_scan2() {
    if (threadIdx.x == 0) {
        int run = 0;
        for (int b = 0; b < kSB; b++) { g_boff[b] = run; run += g_bsum[b]; }
        g_rowptr[kN] = run;
    }
}

__global__ void k_scan3() {
    int i = blockIdx.x * 1024 + threadIdx.x;
    if (i < kN) g_rowptr[i] += g_boff[blockIdx.x];
}

__global__ void k_fill(const int* __restrict__ src, const int* __restrict__ dst) {
    int e = blockIdx.x * blockDim.x + threadIdx.x;
    if (e < kE) {
        int d = dst[e], s = src[e];
        int pos = g_rowptr[d] + atomicAdd(&g_cnt[d], 1);
        g_col[pos] = s;
        g_w[pos]   = rsqrtf(fmaxf((float)g_degout[s], 1.0f));
    }
}

// ---------------- input GEMM: h0 = relu(X[50000,512] @ W[512,64] + b) ----------------
constexpr int FSTR = 68;

__global__ void k_ingemm(const float* __restrict__ X, const float* __restrict__ W,
                         const float* __restrict__ bias) {
    __shared__ float Fs[32 * FSTR];
    __shared__ float Ws[32 * FSTR];
    int tid  = threadIdx.x;
    int tcol = tid & 15;
    int trow = tid >> 4;
    int row0 = blockIdx.x * 64;
    float acc[4][4] = {};

    for (int kc = 0; kc < kIN; kc += 32) {
        #pragma unroll
        for (int i = 0; i < 2; i++) {
            int fid = tid + i * 256;
            int r   = fid >> 3;
            int k4  = fid & 7;
            int grow = row0 + r;
            float4 v = make_float4(0.f, 0.f, 0.f, 0.f);
            if (grow < kN) v = *(const float4*)&X[grow * kIN + kc + k4 * 4];
            Fs[(k4 * 4 + 0) * FSTR + r] = v.x;
            Fs[(k4 * 4 + 1) * FSTR + r] = v.y;
            Fs[(k4 * 4 + 2) * FSTR + r] = v.z;
            Fs[(k4 * 4 + 3) * FSTR + r] = v.w;
        }
        #pragma unroll
        for (int i = 0; i < 2; i++) {
            int fid = tid + i * 256;
            int k   = fid >> 4;
            int c4  = fid & 15;
            *(float4*)&Ws[k * FSTR + c4 * 4] = *(const float4*)&W[(kc + k) * kHID + c4 * 4];
        }
        __syncthreads();
        #pragma unroll 8
        for (int k = 0; k < 32; k++) {
            float4 a = *(float4*)&Fs[k * FSTR + trow * 4];
            float4 b = *(float4*)&Ws[k * FSTR + tcol * 4];
            float av[4] = {a.x, a.y, a.z, a.w};
            float bv[4] = {b.x, b.y, b.z, b.w};
            #pragma unroll
            for (int i = 0; i < 4; i++)
                #pragma unroll
                for (int j = 0; j < 4; j++)
                    acc[i][j] += av[i] * bv[j];
        }
        __syncthreads();
    }
    #pragma unroll
    for (int i = 0; i < 4; i++) {
        int grow = row0 + trow * 4 + i;
        if (grow < kN) {
            float4 o;
            o.x = fmaxf(acc[i][0] + bias[tcol * 4 + 0], 0.f);
            o.y = fmaxf(acc[i][1] + bias[tcol * 4 + 1], 0.f);
            o.z = fmaxf(acc[i][2] + bias[tcol * 4 + 2], 0.f);
            o.w = fmaxf(acc[i][3] + bias[tcol * 4 + 3], 0.f);
            *(float4*)&g_h0[grow * kHID + tcol * 4] = o;
        }
    }
}

// ---------------- fused layer: SpMM (gather) -> hout = relu(f@M1 + h0@M2 + bias) ------
// Reads hin (previous layer, never written this launch), writes hout (disjoint buffer).
// smem layout (floats): Fs[0..4095] F0s[4096..8191] M1s[8192..12287] M2s[12288..16383]
//                       bs[16384..16447]
constexpr int LG_SMEM = (4 * 64 * 64 + 64) * (int)sizeof(float);   // 65792 B

__global__ __launch_bounds__(256, 3)
void k_layer(const float* __restrict__ hin, float* __restrict__ hout,
             int l, const float* __restrict__ bias) {
    extern __shared__ float sm[];
    float* Fs  = sm;
    float* F0s = sm + 4096;
    float* M1s = sm + 8192;
    float* M2s = sm + 12288;
    float* bs  = sm + 16384;
    int tid  = threadIdx.x;
    int lane = tid & 31;
    int wid  = tid >> 5;
    int row0 = blockIdx.x * 64;
    const float* __restrict__ M1g = g_M1 + l * kHID * kHID;
    const float* __restrict__ M2g = g_M2 + l * kHID * kHID;
    const float2* __restrict__ h2 = (const float2*)hin;

    // ---- stage h0 tile + M1 + M2 + bias via cp.async (overlaps with SpMM) ----
    unsigned int sbase = (unsigned int)__cvta_generic_to_shared(sm);
    #pragma unroll
    for (int it = 0; it < 4; it++) {
        int s  = tid + it * 256;            // 0..1023 float4 slots
        int r  = s >> 4;
        int c4 = s & 15;
        int g  = row0 + r; if (g >= kN) g = kN - 1;
        cpasync16(sbase + 16384u + s * 16u, &g_h0[g * kHID + c4 * 4]);
        cpasync16(sbase + 32768u + s * 16u, &M1g[s * 4]);
        cpasync16(sbase + 49152u + s * 16u, &M2g[s * 4]);
    }
    if (tid < 16) cpasync16(sbase + 65536u + tid * 16u, &bias[tid * 4]);
    asm volatile("cp.async.commit_group;\n" ::: "memory");

    // ---- SpMM: each warp gathers 8 dst rows into Fs (row-major) ----
    #pragma unroll 1
    for (int rr = 0; rr < 8; rr++) {
        int r = wid * 8 + rr;
        int g = row0 + r;
        if (g >= kN) break;
        int beg = g_rowptr[g], end = g_rowptr[g + 1];
        float cd = 0.9f * rsqrtf(fmaxf((float)(end - beg), 1.0f));
        float ax = 0.f, ay = 0.f;
        int e = beg;
        for (; e + 4 <= end; e += 4) {
            int   c0 = g_col[e],   c1 = g_col[e+1], c2 = g_col[e+2], c3 = g_col[e+3];
            float w0 = g_w[e],     w1 = g_w[e+1],   w2 = g_w[e+2],   w3 = g_w[e+3];
            float2 v0 = h2[c0 * 32 + lane];
            float2 v1 = h2[c1 * 32 + lane];
            float2 v2 = h2[c2 * 32 + lane];
            float2 v3 = h2[c3 * 32 + lane];
            ax += w0 * v0.x + w1 * v1.x + w2 * v2.x + w3 * v3.x;
            ay += w0 * v0.y + w1 * v1.y + w2 * v2.y + w3 * v3.y;
        }
        for (; e < end; e++) {
            int c = g_col[e]; float w = g_w[e];
            float2 v = h2[c * 32 + lane];
            ax += w * v.x; ay += w * v.y;
        }
        ((float2*)Fs)[r * 32 + lane] = make_float2(cd * ax, cd * ay);
    }

    asm volatile("cp.async.wait_group 0;\n" ::: "memory");
    __syncthreads();

    // ---- GEMM: 4x4 register block, packed f32x2 FMAs ----
    int tcol = tid & 15;
    int trow = tid >> 4;
    unsigned long long acc2[4][2] = {};   // (0.f,0.f) pairs
    #pragma unroll
    for (int k = 0; k < 64; k += 4) {
        float4 a[4], a0[4];
        #pragma unroll
        for (int i = 0; i < 4; i++) {
            a[i]  = *(const float4*)&Fs [(trow * 4 + i) * 64 + k];
            a0[i] = *(const float4*)&F0s[(trow * 4 + i) * 64 + k];
        }
        #pragma unroll
        for (int kk = 0; kk < 4; kk++) {
            ulonglong2 b1 = *(const ulonglong2*)&M1s[(k + kk) * 64 + tcol * 4];
            ulonglong2 b2 = *(const ulonglong2*)&M2s[(k + kk) * 64 + tcol * 4];
            #pragma unroll
            for (int i = 0; i < 4; i++) {
                unsigned long long av  = pack2(((const float*)&a [i])[kk]);
                unsigned long long a0v = pack2(((const float*)&a0[i])[kk]);
                acc2[i][0] = fma2(av,  b1.x, acc2[i][0]);
                acc2[i][1] = fma2(av,  b1.y, acc2[i][1]);
                acc2[i][0] = fma2(a0v, b2.x, acc2[i][0]);
                acc2[i][1] = fma2(a0v, b2.y, acc2[i][1]);
            }
        }
    }
    #pragma unroll
    for (int i = 0; i < 4; i++) {
        int grow = row0 + trow * 4 + i;
        if (grow < kN) {
            float2 p0 = unpack2(acc2[i][0]);
            float2 p1 = unpack2(acc2[i][1]);
            float4 o;
            o.x = fmaxf(p0.x + bs[tcol * 4 + 0], 0.f);
            o.y = fmaxf(p0.y + bs[tcol * 4 + 1], 0.f);
            o.z = fmaxf(p1.x + bs[tcol * 4 + 2], 0.f);
            o.w = fmaxf(p1.y + bs[tcol * 4 + 3], 0.f);
            *(float4*)&hout[grow * kHID + tcol * 4] = o;
        }
    }
}

// ---------------- output: log_softmax(h @ W_out + b_out) ----------------
__global__ void k_out(const float* __restrict__ hfin, const float* __restrict__ Wo,
                      const float* __restrict__ bo, float* __restrict__ out) {
    __shared__ float Ws[kHID * kOUT];
    __shared__ float bs[kOUT];
    int tid = threadIdx.x;
    for (int i = tid; i < kHID * kOUT; i += 256) Ws[i] = Wo[i];
    if (tid < kOUT) bs[tid] = bo[tid];
    __syncthreads();
    int warp = tid >> 5;
    int lane = tid & 31;
    int node = blockIdx.x * 8 + warp;
    if (node >= kN) return;
    float2 hv = ((const float2*)hfin)[node * 32 + lane];
    float acc0 = bs[lane];
    float acc1 = (lane < 8) ? bs[32 + lane] : 0.f;
    #pragma unroll
    for (int k = 0; k < kHID; k++) {
        float val = __shfl_sync(0xffffffffu, (k & 1) ? hv.y : hv.x, k >> 1);
        acc0 += val * Ws[k * kOUT + lane];
        if (lane < 8) acc1 += val * Ws[k * kOUT + 32 + lane];
    }
    float m = fmaxf(acc0, (lane < 8) ? acc1 : -INFINITY);
    #pragma unroll
    for (int off = 16; off > 0; off >>= 1)
        m = fmaxf(m, __shfl_xor_sync(0xffffffffu, m, off));
    float s = expf(acc0 - m) + ((lane < 8) ? expf(acc1 - m) : 0.f);
    #pragma unroll
    for (int off = 16; off > 0; off >>= 1)
        s += __shfl_xor_sync(0xffffffffu, s, off);
    float lse = m + logf(s);
    out[node * kOUT + lane] = acc0 - lse;
    if (lane < 8) out[node * kOUT + 32 + lane] = acc1 - lse;
}

// ---------------- launch ----------------
extern "C" void kernel_launch(void* const* d_in, const int* in_sizes, int n_in,
                              void* d_out, int out_size) {
    const float* features = (const float*)d_in[0];
    const float* W_in     = (const float*)d_in[1];
    const float* b_in     = (const float*)d_in[2];
    const float* W1       = (const float*)d_in[3];
    const float* W2       = (const float*)d_in[4];
    const float* b        = (const float*)d_in[5];
    const float* W_out    = (const float*)d_in[6];
    const float* b_out    = (const float*)d_in[7];
    const int*   src      = (const int*)d_in[8];
    const int*   dst      = (const int*)d_in[9];
    float* out = (float*)d_out;

    cudaFuncSetAttribute(k_layer, cudaFuncAttributeMaxDynamicSharedMemorySize, LG_SMEM);

    // resolve device-global addresses for ping-pong buffers
    float *hA, *hB, *h0;
    cudaGetSymbolAddress((void**)&hA, g_hA);
    cudaGetSymbolAddress((void**)&hB, g_hB);
    cudaGetSymbolAddress((void**)&h0, g_h0);

    int gridI = (kL * kHID * kHID + 255) / 256;   // covers kN too (65536 > 50000)
    int gridE = (kE + 255) / 256;
    int gridG = (kN + 63) / 64;                   // 782 tiles
    int gridS = (kN + 7) / 8;

    k_init  <<<gridI, 256>>>(W1, W2);
    k_degree<<<gridE, 256>>>(src, dst);
    k_scan1 <<<kSB, 1024>>>();
    k_scan2 <<<1, 32>>>();
    k_scan3 <<<kSB, 1024>>>();
    k_fill  <<<gridE, 256>>>(src, dst);
    k_ingemm<<<gridG, 256>>>(features, W_in, b_in);

    // ping-pong: layer l reads (l==0 ? h0 : buf[(l-1)&1]), writes buf[l&1]
    for (int l = 0; l < kL; l++) {
        const float* hin = (l == 0) ? h0 : ((l & 1) ? hA : hB);
        float*       ho  = (l & 1) ? hB : hA;
        k_layer<<<gridG, 256, LG_SMEM>>>(hin, ho, l, b + l * kHID);
    }
    // after layer 15 (odd), result is in hB
    k_out<<<gridS, 256>>>(hB, W_out, b_out, out);
}